// round 5
// baseline (speedup 1.0000x reference)
#include <cuda_runtime.h>
#include <cuda_fp16.h>

#define B    4
#define LQ   512
#define LK   512
#define E    128
#define D    256
#define TL   8            // l-rows per score/context CTA
#define QT   32           // qq per stage tile
#define QBLK 256          // qq per score-CTA
#define NTA  (QBLK / QT)  // 8 tiles per score-CTA
#define NTHR 256

// Scratch for projected q/k (allocation-free rule: __device__ globals)
__device__ float g_qproj[B * LQ * E];
__device__ float g_kproj[B * LK * E];

typedef unsigned long long ull;

__device__ __forceinline__ __half2 tanh_h2(__half2 x) {
    unsigned xu = *reinterpret_cast<unsigned*>(&x);
    unsigned r;
    asm("tanh.approx.f16x2 %0, %1;" : "=r"(r) : "r"(xu));
    return *reinterpret_cast<__half2*>(&r);
}
__device__ __forceinline__ ull pk(float a, float b) {
    ull r; asm("mov.b64 %0, {%1, %2};" : "=l"(r) : "f"(a), "f"(b)); return r;
}
__device__ __forceinline__ float2 upk(ull v) {
    float2 r; asm("mov.b64 {%0, %1}, %2;" : "=f"(r.x), "=f"(r.y) : "l"(v)); return r;
}
__device__ __forceinline__ ull fmax2(ull a, ull b, ull c) {
    ull r; asm("fma.rn.f32x2 %0, %1, %2, %3;" : "=l"(r) : "l"(a), "l"(b), "l"(c)); return r;
}
__device__ __forceinline__ void cpasync16(void* smem_dst, const void* gsrc) {
    unsigned s = (unsigned)__cvta_generic_to_shared(smem_dst);
    asm volatile("cp.async.cg.shared.global [%0], [%1], 16;" :: "r"(s), "l"(gsrc));
}

// ---------------------------------------------------------------------------
// Projection: out[r][e] = sum_d X[r][d] * W[d][e]
// ---------------------------------------------------------------------------
__global__ __launch_bounds__(128) void proj_kernel(
    const float* __restrict__ query, const float* __restrict__ key,
    const float* __restrict__ Wc1,   const float* __restrict__ Wc2)
{
    const float* X; const float* W; float* O;
    if (blockIdx.y == 0) { X = query; W = Wc1; O = g_qproj; }
    else                 { X = key;   W = Wc2; O = g_kproj; }

    const int row0 = blockIdx.x * 4;
    const int tid  = threadIdx.x;   // == e

    __shared__ float xs[4 * D];
    const float4* xv = (const float4*)(X + (size_t)row0 * D);
    #pragma unroll
    for (int i = tid; i < 4 * D / 4; i += 128)
        ((float4*)xs)[i] = xv[i];
    __syncthreads();

    float a0 = 0.f, a1 = 0.f, a2 = 0.f, a3 = 0.f;
    #pragma unroll 8
    for (int d = 0; d < D; d++) {
        float w = W[d * E + tid];
        a0 += xs[d      ] * w;
        a1 += xs[D  + d ] * w;
        a2 += xs[2*D + d] * w;
        a3 += xs[3*D + d] * w;
    }
    O[(size_t)(row0 + 0) * E + tid] = a0;
    O[(size_t)(row0 + 1) * E + tid] = a1;
    O[(size_t)(row0 + 2) * E + tid] = a2;
    O[(size_t)(row0 + 3) * E + tid] = a3;
}

// ---------------------------------------------------------------------------
// Kernel A: raw scores. Grid (LQ/QBLK=2, LK/TL=64, B=4) = 512 CTAs, 256 thr.
// Each CTA: scores for TL=8 l-rows x QBLK=256 qq. lane = (lrow=lane>>2,
// qoff=lane&3); warp w owns qq = w*4+qoff in each 32-qq tile.
// q LDS 4 rows x 16B (8-way dup), k LDS 8 rows x 16B (4-way dup), padded rows.
// tanh via MUFU f16x2; scores written straight to att_out (raw).
// ---------------------------------------------------------------------------
__global__ __launch_bounds__(NTHR, 4) void score_kernel(
    const float* __restrict__ vc, float* __restrict__ att_out)
{
    const int qblk = blockIdx.x;
    const int l0   = blockIdx.y * TL;
    const int b    = blockIdx.z;
    const int tid  = threadIdx.x;
    const int w    = tid >> 5;
    const int lane = tid & 31;

    __shared__ float   ks[TL][132];      // 4.2 KB padded
    __shared__ __half2 vcs[E / 2];       // 256 B
    __shared__ float   qs[2][QT][132];   // 33.8 KB double buffer, padded

    for (int i = tid; i < TL * E; i += NTHR)
        ks[i >> 7][i & 127] = g_kproj[(size_t)(b * LK + l0 + (i >> 7)) * E + (i & 127)];
    if (tid < E / 2)
        vcs[tid] = __floats2half2_rn(vc[2 * tid], vc[2 * tid + 1]);

    const float4* qbase = (const float4*)(g_qproj + ((size_t)b * LQ + qblk * QBLK) * E);

    #pragma unroll
    for (int j = 0; j < 4; j++) {
        int i = tid + j * NTHR;                          // 0..1023 float4s
        cpasync16(&qs[0][i >> 5][(i & 31) * 4], qbase + i);
    }
    asm volatile("cp.async.commit_group;");

    const int lrow = lane >> 2;              // 0..7
    const int qrow = w * 4 + (lane & 3);     // 0..31 within tile
    float* orow = att_out + (size_t)(b * LK + l0 + lrow) * LQ + qblk * QBLK + qrow;

    #pragma unroll 1
    for (int t = 0; t < NTA; t++) {
        __syncthreads();
        if (t + 1 < NTA) {
            const float4* src = qbase + (t + 1) * (QT * E / 4);
            #pragma unroll
            for (int j = 0; j < 4; j++) {
                int i = tid + j * NTHR;
                cpasync16(&qs[(t + 1) & 1][i >> 5][(i & 31) * 4], src + i);
            }
            asm volatile("cp.async.commit_group;");
            asm volatile("cp.async.wait_group 1;");
        } else {
            asm volatile("cp.async.wait_group 0;");
        }
        __syncthreads();

        const float4* qp = (const float4*)qs[t & 1][qrow];
        const float4* kp = (const float4*)ks[lrow];
        const uint2*  vp = (const uint2*)vcs;

        float facc = 0.f;
        #pragma unroll 4
        for (int c = 0; c < E / 16; c++) {               // 8 chunks of 16 e
            __half2 acc01 = __float2half2_rn(0.f);
            __half2 acc23 = __float2half2_rn(0.f);
            #pragma unroll
            for (int u = 0; u < 4; u++) {
                const int e4 = c * 4 + u;
                float4 q = qp[e4];
                float4 k = kp[e4];
                uint2  v = vp[e4];
                __half2 h01 = __floats2half2_rn(q.x + k.x, q.y + k.y);
                __half2 h23 = __floats2half2_rn(q.z + k.z, q.w + k.w);
                __half2 t01 = tanh_h2(h01);
                __half2 t23 = tanh_h2(h23);
                __half2 v01 = *reinterpret_cast<__half2*>(&v.x);
                __half2 v23 = *reinterpret_cast<__half2*>(&v.y);
                acc01 = __hfma2(v01, t01, acc01);
                acc23 = __hfma2(v23, t23, acc23);
            }
            float2 f01 = __half22float2(acc01);
            float2 f23 = __half22float2(acc23);
            facc += (f01.x + f01.y) + (f23.x + f23.y);
        }
        orow[t * QT] = facc;                              // raw score
    }
}

// ---------------------------------------------------------------------------
// Kernel B: softmax in place over qq. Grid (LK/TL=64, B) = 256 CTAs, 256 thr;
// warp w owns row l0 + w. float4 I/O.
// ---------------------------------------------------------------------------
__global__ __launch_bounds__(NTHR) void softmax_kernel(float* __restrict__ att)
{
    const int b    = blockIdx.y;
    const int l    = blockIdx.x * TL + (threadIdx.x >> 5);
    const int lane = threadIdx.x & 31;

    float4* row = (float4*)(att + (size_t)(b * LK + l) * LQ);

    float4 v[4];
    float m = -1e30f;
    #pragma unroll
    for (int k = 0; k < 4; k++) {
        v[k] = row[lane + 32 * k];
        m = fmaxf(m, fmaxf(fmaxf(v[k].x, v[k].y), fmaxf(v[k].z, v[k].w)));
    }
    #pragma unroll
    for (int o = 16; o; o >>= 1) m = fmaxf(m, __shfl_xor_sync(0xffffffffu, m, o));
    float s = 0.f;
    #pragma unroll
    for (int k = 0; k < 4; k++) {
        v[k].x = __expf(v[k].x - m); v[k].y = __expf(v[k].y - m);
        v[k].z = __expf(v[k].z - m); v[k].w = __expf(v[k].w - m);
        s += (v[k].x + v[k].y) + (v[k].z + v[k].w);
    }
    #pragma unroll
    for (int o = 16; o; o >>= 1) s += __shfl_xor_sync(0xffffffffu, s, o);
    const float inv = __fdividef(1.f, s);
    #pragma unroll
    for (int k = 0; k < 4; k++) {
        v[k].x *= inv; v[k].y *= inv; v[k].z *= inv; v[k].w *= inv;
        row[lane + 32 * k] = v[k];
    }
}

// ---------------------------------------------------------------------------
// Kernel C: context = atten @ value.
// Grid (D/128=2, LK/TL=64, B) = 512 CTAs, 256 thr.
// Probs staged in smem; thread = (d4c = tid&31 within 128-col slice,
// lg = tid>>5 = l-row). f32x2 FMA.
// ---------------------------------------------------------------------------
__global__ __launch_bounds__(NTHR) void context_kernel(
    const float* __restrict__ value, const float* __restrict__ att,
    float* __restrict__ ctx_out)
{
    const int dsl = blockIdx.x;              // 0..1: d-slice of 128 cols
    const int l0  = blockIdx.y * TL;
    const int b   = blockIdx.z;
    const int tid = threadIdx.x;

    __shared__ float ps[TL][LQ];             // 16 KB probabilities

    const float4* arow = (const float4*)(att + (size_t)(b * LK + l0) * LQ);
    #pragma unroll
    for (int j = 0; j < 4; j++) {            // 1024 float4 / 256 thr
        int i = tid + j * NTHR;              // row = i>>7, col4 = i&127
        ((float4*)ps)[ (i >> 7) * (LQ / 4) + (i & 127) ] = arow[(i >> 7) * (LQ / 4) + (i & 127)];
    }
    __syncthreads();

    const int d4c = tid & 31;                // float4 col within slice
    const int lg  = tid >> 5;                // l-row 0..7
    const float4* vbase = (const float4*)(value + (size_t)b * LQ * D) + dsl * 32 + d4c;

    ull a0 = pk(0.f, 0.f), a1 = pk(0.f, 0.f);
    #pragma unroll 8
    for (int qq = 0; qq < LQ; qq++) {
        float4 v = vbase[qq * (D / 4)];      // coalesced 512B/warp
        float  p = ps[lg][qq];               // broadcast
        ull p2 = pk(p, p);
        a0 = fmax2(p2, pk(v.x, v.y), a0);
        a1 = fmax2(p2, pk(v.z, v.w), a1);
    }
    float2 f0 = upk(a0), f1 = upk(a1);
    ((float4*)ctx_out)[((size_t)(b * LK + l0 + lg) * D) / 4 + dsl * 32 + d4c] =
        make_float4(f0.x, f0.y, f1.x, f1.y);
}

// ---------------------------------------------------------------------------
extern "C" void kernel_launch(void* const* d_in, const int* in_sizes, int n_in,
                              void* d_out, int out_size)
{
    const float* query = (const float*)d_in[0];
    const float* key   = (const float*)d_in[1];
    const float* value = (const float*)d_in[2];
    const float* Wc1   = (const float*)d_in[3];
    const float* Wc2   = (const float*)d_in[4];
    const float* vc    = (const float*)d_in[5];

    float* ctx = (float*)d_out;                 // [B, LK, D]
    float* att = ctx + (size_t)B * LK * D;      // [B, LK, LQ]

    proj_kernel<<<dim3(B * LQ / 4, 2), 128>>>(query, key, Wc1, Wc2);
    score_kernel<<<dim3(LQ / QBLK, LK / TL, B), NTHR>>>(vc, att);
    softmax_kernel<<<dim3(LK / TL, B), NTHR>>>(att);
    context_kernel<<<dim3(D / 128, LK / TL, B), NTHR>>>(value, att, ctx);
}

// round 6
// speedup vs baseline: 1.3490x; 1.3490x over previous
#include <cuda_runtime.h>
#include <cuda_fp16.h>

#define B    4
#define LQ   512
#define LK   512
#define E    128
#define D    256
#define TL   8            // l-rows per score/context CTA
#define QT   32           // qq per stage tile
#define QBLK 256          // qq per score-CTA
#define NTA  (QBLK / QT)  // 8 tiles per score-CTA
#define NTHR 256

// Scratch for projected q/k (allocation-free rule: __device__ globals)
__device__ float g_qproj[B * LQ * E];
__device__ float g_kproj[B * LK * E];

typedef unsigned long long ull;

__device__ __forceinline__ __half2 tanh_h2(__half2 x) {
    unsigned xu = *reinterpret_cast<unsigned*>(&x);
    unsigned r;
    asm("tanh.approx.f16x2 %0, %1;" : "=r"(r) : "r"(xu));
    return *reinterpret_cast<__half2*>(&r);
}
__device__ __forceinline__ void cpasync16(void* smem_dst, const void* gsrc) {
    unsigned s = (unsigned)__cvta_generic_to_shared(smem_dst);
    asm volatile("cp.async.cg.shared.global [%0], [%1], 16;" :: "r"(s), "l"(gsrc));
}

// ---------------------------------------------------------------------------
// Projection: out[r][e] = sum_d X[r][d] * W[d][e]
// ---------------------------------------------------------------------------
__global__ __launch_bounds__(128) void proj_kernel(
    const float* __restrict__ query, const float* __restrict__ key,
    const float* __restrict__ Wc1,   const float* __restrict__ Wc2)
{
    const float* X; const float* W; float* O;
    if (blockIdx.y == 0) { X = query; W = Wc1; O = g_qproj; }
    else                 { X = key;   W = Wc2; O = g_kproj; }

    const int row0 = blockIdx.x * 4;
    const int tid  = threadIdx.x;   // == e

    __shared__ float xs[4 * D];
    const float4* xv = (const float4*)(X + (size_t)row0 * D);
    #pragma unroll
    for (int i = tid; i < 4 * D / 4; i += 128)
        ((float4*)xs)[i] = xv[i];
    __syncthreads();

    float a0 = 0.f, a1 = 0.f, a2 = 0.f, a3 = 0.f;
    #pragma unroll 8
    for (int d = 0; d < D; d++) {
        float w = W[d * E + tid];
        a0 += xs[d      ] * w;
        a1 += xs[D  + d ] * w;
        a2 += xs[2*D + d] * w;
        a3 += xs[3*D + d] * w;
    }
    O[(size_t)(row0 + 0) * E + tid] = a0;
    O[(size_t)(row0 + 1) * E + tid] = a1;
    O[(size_t)(row0 + 2) * E + tid] = a2;
    O[(size_t)(row0 + 3) * E + tid] = a3;
}

// ---------------------------------------------------------------------------
// Kernel A: raw scores. Grid (LQ/QBLK=2, LK/TL=64, B=4) = 512 CTAs, 256 thr.
// (unchanged from R5 — measured ~9us, near MUFU floor)
// ---------------------------------------------------------------------------
__global__ __launch_bounds__(NTHR, 4) void score_kernel(
    const float* __restrict__ vc, float* __restrict__ att_out)
{
    const int qblk = blockIdx.x;
    const int l0   = blockIdx.y * TL;
    const int b    = blockIdx.z;
    const int tid  = threadIdx.x;
    const int w    = tid >> 5;
    const int lane = tid & 31;

    __shared__ float   ks[TL][132];      // 4.2 KB padded
    __shared__ __half2 vcs[E / 2];       // 256 B
    __shared__ float   qs[2][QT][132];   // 33.8 KB double buffer, padded

    for (int i = tid; i < TL * E; i += NTHR)
        ks[i >> 7][i & 127] = g_kproj[(size_t)(b * LK + l0 + (i >> 7)) * E + (i & 127)];
    if (tid < E / 2)
        vcs[tid] = __floats2half2_rn(vc[2 * tid], vc[2 * tid + 1]);

    const float4* qbase = (const float4*)(g_qproj + ((size_t)b * LQ + qblk * QBLK) * E);

    #pragma unroll
    for (int j = 0; j < 4; j++) {
        int i = tid + j * NTHR;                          // 0..1023 float4s
        cpasync16(&qs[0][i >> 5][(i & 31) * 4], qbase + i);
    }
    asm volatile("cp.async.commit_group;");

    const int lrow = lane >> 2;              // 0..7
    const int qrow = w * 4 + (lane & 3);     // 0..31 within tile
    float* orow = att_out + (size_t)(b * LK + l0 + lrow) * LQ + qblk * QBLK + qrow;

    #pragma unroll 1
    for (int t = 0; t < NTA; t++) {
        __syncthreads();
        if (t + 1 < NTA) {
            const float4* src = qbase + (t + 1) * (QT * E / 4);
            #pragma unroll
            for (int j = 0; j < 4; j++) {
                int i = tid + j * NTHR;
                cpasync16(&qs[(t + 1) & 1][i >> 5][(i & 31) * 4], src + i);
            }
            asm volatile("cp.async.commit_group;");
            asm volatile("cp.async.wait_group 1;");
        } else {
            asm volatile("cp.async.wait_group 0;");
        }
        __syncthreads();

        const float4* qp = (const float4*)qs[t & 1][qrow];
        const float4* kp = (const float4*)ks[lrow];
        const uint2*  vp = (const uint2*)vcs;

        float facc = 0.f;
        #pragma unroll 4
        for (int c = 0; c < E / 16; c++) {               // 8 chunks of 16 e
            __half2 acc01 = __float2half2_rn(0.f);
            __half2 acc23 = __float2half2_rn(0.f);
            #pragma unroll
            for (int u = 0; u < 4; u++) {
                const int e4 = c * 4 + u;
                float4 q = qp[e4];
                float4 k = kp[e4];
                uint2  v = vp[e4];
                __half2 h01 = __floats2half2_rn(q.x + k.x, q.y + k.y);
                __half2 h23 = __floats2half2_rn(q.z + k.z, q.w + k.w);
                __half2 t01 = tanh_h2(h01);
                __half2 t23 = tanh_h2(h23);
                __half2 v01 = *reinterpret_cast<__half2*>(&v.x);
                __half2 v23 = *reinterpret_cast<__half2*>(&v.y);
                acc01 = __hfma2(v01, t01, acc01);
                acc23 = __hfma2(v23, t23, acc23);
            }
            float2 f01 = __half22float2(acc01);
            float2 f23 = __half22float2(acc23);
            facc += (f01.x + f01.y) + (f23.x + f23.y);
        }
        orow[t * QT] = facc;                              // raw score
    }
}

// ---------------------------------------------------------------------------
// Kernel B: softmax in place over qq. Grid (LK/TL=64, B) = 256 CTAs, 256 thr.
// ---------------------------------------------------------------------------
__global__ __launch_bounds__(NTHR) void softmax_kernel(float* __restrict__ att)
{
    const int b    = blockIdx.y;
    const int l    = blockIdx.x * TL + (threadIdx.x >> 5);
    const int lane = threadIdx.x & 31;

    float4* row = (float4*)(att + (size_t)(b * LK + l) * LQ);

    float4 v[4];
    float m = -1e30f;
    #pragma unroll
    for (int k = 0; k < 4; k++) {
        v[k] = row[lane + 32 * k];
        m = fmaxf(m, fmaxf(fmaxf(v[k].x, v[k].y), fmaxf(v[k].z, v[k].w)));
    }
    #pragma unroll
    for (int o = 16; o; o >>= 1) m = fmaxf(m, __shfl_xor_sync(0xffffffffu, m, o));
    float s = 0.f;
    #pragma unroll
    for (int k = 0; k < 4; k++) {
        v[k].x = __expf(v[k].x - m); v[k].y = __expf(v[k].y - m);
        v[k].z = __expf(v[k].z - m); v[k].w = __expf(v[k].w - m);
        s += (v[k].x + v[k].y) + (v[k].z + v[k].w);
    }
    #pragma unroll
    for (int o = 16; o; o >>= 1) s += __shfl_xor_sync(0xffffffffu, s, o);
    const float inv = __fdividef(1.f, s);
    #pragma unroll
    for (int k = 0; k < 4; k++) {
        v[k].x *= inv; v[k].y *= inv; v[k].z *= inv; v[k].w *= inv;
        row[lane + 32 * k] = v[k];
    }
}

// ---------------------------------------------------------------------------
// Kernel C: context = atten @ value, register-tiled.
// Grid (LK/TL=64, B) = 256 CTAs, 256 thr.
// thread = (d4 = tid&63 -> float4 col of D, qg = tid>>6 -> qq quarter).
// Each thread accumulates ALL 8 l-rows (8 float4 regs) over its 128 qq:
// one value load feeds 8 rows -> 128 FLOP / 64B. 4-way partials reduced
// through smem, coalesced float4 stores.
// ---------------------------------------------------------------------------
__global__ __launch_bounds__(NTHR) void context_kernel(
    const float* __restrict__ value, const float* __restrict__ att,
    float* __restrict__ ctx_out)
{
    const int l0  = blockIdx.x * TL;
    const int b   = blockIdx.y;
    const int tid = threadIdx.x;
    const int d4  = tid & 63;            // float4 column 0..63 (full D)
    const int qg  = tid >> 6;            // 0..3 qq quarter

    __shared__ float  ps[TL][LQ];        // 16 KB probabilities
    __shared__ float4 red[4][TL][64];    // 32 KB partial accumulators

    // stage probs (8 rows x 512 = 1024 float4)
    const float4* arow = (const float4*)(att + (size_t)(b * LK + l0) * LQ);
    #pragma unroll
    for (int j = 0; j < 4; j++)
        ((float4*)ps)[tid + j * NTHR] = arow[tid + j * NTHR];
    __syncthreads();

    const float4* vbase = (const float4*)(value + (size_t)b * LQ * D) + d4;

    float4 acc[TL];
    #pragma unroll
    for (int l = 0; l < TL; l++) acc[l] = make_float4(0.f, 0.f, 0.f, 0.f);

    const int q0 = qg * (LQ / 4);        // 128-qq quarter
    #pragma unroll 2
    for (int qc = 0; qc < LQ / 4; qc += 4) {
        const int qq = q0 + qc;
        float4 v0 = vbase[(qq + 0) * (D / 4)];
        float4 v1 = vbase[(qq + 1) * (D / 4)];
        float4 v2 = vbase[(qq + 2) * (D / 4)];
        float4 v3 = vbase[(qq + 3) * (D / 4)];
        #pragma unroll
        for (int l = 0; l < TL; l++) {
            float4 p = *(const float4*)&ps[l][qq];   // broadcast LDS.128
            acc[l].x += p.x * v0.x; acc[l].y += p.x * v0.y;
            acc[l].z += p.x * v0.z; acc[l].w += p.x * v0.w;
            acc[l].x += p.y * v1.x; acc[l].y += p.y * v1.y;
            acc[l].z += p.y * v1.z; acc[l].w += p.y * v1.w;
            acc[l].x += p.z * v2.x; acc[l].y += p.z * v2.y;
            acc[l].z += p.z * v2.z; acc[l].w += p.z * v2.w;
            acc[l].x += p.w * v3.x; acc[l].y += p.w * v3.y;
            acc[l].z += p.w * v3.z; acc[l].w += p.w * v3.w;
        }
    }

    // write partials
    #pragma unroll
    for (int l = 0; l < TL; l++)
        red[qg][l][d4] = acc[l];
    __syncthreads();

    // thread (d4, qg) reduces + stores l-rows {2*qg, 2*qg+1}
    #pragma unroll
    for (int j = 0; j < 2; j++) {
        const int l = qg * 2 + j;
        float4 r0 = red[0][l][d4], r1 = red[1][l][d4];
        float4 r2 = red[2][l][d4], r3 = red[3][l][d4];
        float4 c = make_float4((r0.x + r1.x) + (r2.x + r3.x),
                               (r0.y + r1.y) + (r2.y + r3.y),
                               (r0.z + r1.z) + (r2.z + r3.z),
                               (r0.w + r1.w) + (r2.w + r3.w));
        ((float4*)ctx_out)[(size_t)(b * LK + l0 + l) * (D / 4) + d4] = c;
    }
}

// ---------------------------------------------------------------------------
extern "C" void kernel_launch(void* const* d_in, const int* in_sizes, int n_in,
                              void* d_out, int out_size)
{
    const float* query = (const float*)d_in[0];
    const float* key   = (const float*)d_in[1];
    const float* value = (const float*)d_in[2];
    const float* Wc1   = (const float*)d_in[3];
    const float* Wc2   = (const float*)d_in[4];
    const float* vc    = (const float*)d_in[5];

    float* ctx = (float*)d_out;                 // [B, LK, D]
    float* att = ctx + (size_t)B * LK * D;      // [B, LK, LQ]

    proj_kernel<<<dim3(B * LQ / 4, 2), 128>>>(query, key, Wc1, Wc2);
    score_kernel<<<dim3(LQ / QBLK, LK / TL, B), NTHR>>>(vc, att);
    softmax_kernel<<<dim3(LK / TL, B), NTHR>>>(att);
    context_kernel<<<dim3(LK / TL, B), NTHR>>>(value, att, ctx);
}